// round 1
// baseline (speedup 1.0000x reference)
#include <cuda_runtime.h>
#include <math.h>

#define BB 16
#define CC 512
#define NN 4096
#define KK 64
#define KC 32
#define EPSF 1e-6f

// Scratch (allocation-free per harness rules)
__device__ float g_b[BB * CC * KK];        // current bases  [bi][c][k]
__device__ float g_bnew[BB * CC * KK];     // GEMM2 atomic accumulator
__device__ float g_colsum[BB * KK];        // l1-norm denominators
__device__ float g_attn[(size_t)BB * NN * KK];  // softmaxed attention [bi][n][k] (64MB)

// ---------------------------------------------------------------------------
// Normalize input bases (l2 over C) and broadcast to all batches.
__global__ void k_bases(const float* __restrict__ bases) {
    int k = blockIdx.x, t = threadIdx.x;
    __shared__ float red[128];
    float ss = 0.f;
    for (int c = t; c < CC; c += 128) { float v = bases[c * KK + k]; ss += v * v; }
    red[t] = ss; __syncthreads();
    for (int s = 64; s > 0; s >>= 1) { if (t < s) red[t] += red[t + s]; __syncthreads(); }
    float inv = 1.f / (EPSF + sqrtf(red[0]));
    for (int c = t; c < CC; c += 128) {
        float v = bases[c * KK + k] * inv;
        for (int bi = 0; bi < BB; bi++) g_b[(bi * CC + c) * KK + k] = v;
    }
}

// ---------------------------------------------------------------------------
__global__ void k_zero() {
    int i = blockIdx.x * blockDim.x + threadIdx.x;
    if (i < BB * CC * KK) g_bnew[i] = 0.f;
    if (i < BB * KK) g_colsum[i] = 0.f;
}

// ---------------------------------------------------------------------------
// GEMM1: attn[n,k] = softmax_k( sum_c f[c,n] * b[c,k] ), plus column sums over n.
// Tile 64n x 64k per CTA, 64 threads, 8x8 micro-tile, C reduced in chunks of 32.
__global__ void __launch_bounds__(64) k_gemm1(const float* __restrict__ f) {
    int bi = blockIdx.y, n0 = blockIdx.x * 64;
    int tid = threadIdx.x, tx = tid & 7, ty = tid >> 3;
    __shared__ float As[KC][65];   // As[cc][nn]
    __shared__ float Bs[KC][65];   // Bs[cc][kk]
    __shared__ float s_cs[KK];
    const float* fb = f + (size_t)bi * CC * NN + n0;
    const float* bb = g_b + bi * CC * KK;

    float acc[8][8];
#pragma unroll
    for (int i = 0; i < 8; i++)
#pragma unroll
        for (int j = 0; j < 8; j++) acc[i][j] = 0.f;

    for (int c0 = 0; c0 < CC; c0 += KC) {
        for (int l = tid; l < KC * 64; l += 64) {
            int r = l >> 6, cl = l & 63;
            As[r][cl] = fb[(size_t)(c0 + r) * NN + cl];
            Bs[r][cl] = bb[(c0 + r) * KK + cl];
        }
        __syncthreads();
#pragma unroll 4
        for (int cc = 0; cc < KC; cc++) {
            float a[8], b[8];
#pragma unroll
            for (int i = 0; i < 8; i++) a[i] = As[cc][ty * 8 + i];
#pragma unroll
            for (int j = 0; j < 8; j++) b[j] = Bs[cc][tx * 8 + j];
#pragma unroll
            for (int i = 0; i < 8; i++)
#pragma unroll
                for (int j = 0; j < 8; j++) acc[i][j] += a[i] * b[j];
        }
        __syncthreads();
    }

    if (tid < KK) s_cs[tid] = 0.f;
    __syncthreads();

    // Row softmax over k (thread owns 8 of 64 k's; group of 8 lanes shares a row)
    float* ap = g_attn + ((size_t)bi * NN + n0) * KK;
#pragma unroll
    for (int i = 0; i < 8; i++) {
        float m = acc[i][0];
#pragma unroll
        for (int j = 1; j < 8; j++) m = fmaxf(m, acc[i][j]);
#pragma unroll
        for (int o = 4; o > 0; o >>= 1) m = fmaxf(m, __shfl_xor_sync(0xffffffffu, m, o, 8));
        float s = 0.f;
#pragma unroll
        for (int j = 0; j < 8; j++) { float e = __expf(acc[i][j] - m); acc[i][j] = e; s += e; }
#pragma unroll
        for (int o = 4; o > 0; o >>= 1) s += __shfl_xor_sync(0xffffffffu, s, o, 8);
        float inv = 1.f / s;
#pragma unroll
        for (int j = 0; j < 8; j++) acc[i][j] *= inv;
        float4 v0 = make_float4(acc[i][0], acc[i][1], acc[i][2], acc[i][3]);
        float4 v1 = make_float4(acc[i][4], acc[i][5], acc[i][6], acc[i][7]);
        *(float4*)(ap + (size_t)(ty * 8 + i) * KK + tx * 8) = v0;
        *(float4*)(ap + (size_t)(ty * 8 + i) * KK + tx * 8 + 4) = v1;
    }

    // Column sums (over n) for l1 normalization
#pragma unroll
    for (int j = 0; j < 8; j++) {
        float cs = 0.f;
#pragma unroll
        for (int i = 0; i < 8; i++) cs += acc[i][j];
        atomicAdd(&s_cs[tx * 8 + j], cs);
    }
    __syncthreads();
    if (tid < KK) atomicAdd(&g_colsum[bi * KK + tid], s_cs[tid]);
}

// ---------------------------------------------------------------------------
// GEMM2: bnew[c,k] += sum_n f[c,n] * attn[n,k] / (eps + colsum[k])
// Tile 64c x 64k, N split into 8 ranges of 512 (atomic accumulate).
__global__ void __launch_bounds__(64) k_gemm2(const float* __restrict__ f) {
    int bi = blockIdx.z, c0 = blockIdx.y * 64, nbeg = blockIdx.x * 512;
    int tid = threadIdx.x, tx = tid & 7, ty = tid >> 3;
    __shared__ float As[KC][65];   // As[nn][c]  (transposed f)
    __shared__ float Bs[KC][65];   // Bs[nn][k]
    const float* fb = f + (size_t)bi * CC * NN;
    const float* ap = g_attn + (size_t)bi * NN * KK;

    float acc[8][8];
#pragma unroll
    for (int i = 0; i < 8; i++)
#pragma unroll
        for (int j = 0; j < 8; j++) acc[i][j] = 0.f;

    for (int n0 = nbeg; n0 < nbeg + 512; n0 += KC) {
        for (int l = tid; l < 64 * KC; l += 64) {
            int r = l >> 5, cl = l & 31;                 // r = c row, cl = n col
            As[cl][r] = fb[(size_t)(c0 + r) * NN + n0 + cl];
        }
        for (int l = tid; l < KC * 64; l += 64) {
            int r = l >> 6, cl = l & 63;                 // r = n row, cl = k col
            Bs[r][cl] = ap[(size_t)(n0 + r) * KK + cl];
        }
        __syncthreads();
#pragma unroll 4
        for (int nn = 0; nn < KC; nn++) {
            float a[8], b[8];
#pragma unroll
            for (int i = 0; i < 8; i++) a[i] = As[nn][ty * 8 + i];
#pragma unroll
            for (int j = 0; j < 8; j++) b[j] = Bs[nn][tx * 8 + j];
#pragma unroll
            for (int i = 0; i < 8; i++)
#pragma unroll
                for (int j = 0; j < 8; j++) acc[i][j] += a[i] * b[j];
        }
        __syncthreads();
    }

    float sc[8];
#pragma unroll
    for (int j = 0; j < 8; j++) sc[j] = 1.f / (EPSF + g_colsum[bi * KK + tx * 8 + j]);
    float* bo = g_bnew + (bi * CC + c0) * KK;
#pragma unroll
    for (int i = 0; i < 8; i++)
#pragma unroll
        for (int j = 0; j < 8; j++)
            atomicAdd(&bo[(ty * 8 + i) * KK + tx * 8 + j], acc[i][j] * sc[j]);
}

// ---------------------------------------------------------------------------
// l2-normalize bnew over C -> g_b
__global__ void k_l2() {
    int bi = blockIdx.x >> 6, k = blockIdx.x & 63, t = threadIdx.x;
    __shared__ float red[128];
    const float* src = g_bnew + bi * CC * KK + k;
    float ss = 0.f;
    for (int c = t; c < CC; c += 128) { float v = src[c * KK]; ss += v * v; }
    red[t] = ss; __syncthreads();
    for (int s = 64; s > 0; s >>= 1) { if (t < s) red[t] += red[t + s]; __syncthreads(); }
    float inv = 1.f / (EPSF + sqrtf(red[0]));
    float* dst = g_b + bi * CC * KK + k;
    for (int c = t; c < CC; c += 128) dst[c * KK] = src[c * KK] * inv;
}

// ---------------------------------------------------------------------------
// Reconstruction: out[c,n] = sum_k b[c,k] * attn[n,k]
__global__ void __launch_bounds__(64) k_recon(float* __restrict__ out) {
    int bi = blockIdx.z, c0 = blockIdx.y * 64, n0 = blockIdx.x * 64;
    int tid = threadIdx.x, tx = tid & 7, ty = tid >> 3;
    __shared__ float Bt[KC][65];   // Bt[kk][c]
    __shared__ float At[KC][65];   // At[kk][n]
    const float* bb = g_b + bi * CC * KK;
    const float* ap = g_attn + (size_t)bi * NN * KK;

    float acc[8][8];
#pragma unroll
    for (int i = 0; i < 8; i++)
#pragma unroll
        for (int j = 0; j < 8; j++) acc[i][j] = 0.f;

    for (int k0 = 0; k0 < KK; k0 += KC) {
        for (int l = tid; l < 64 * KC; l += 64) {
            int r = l >> 5, cl = l & 31;                 // r = c row, cl = k col
            Bt[cl][r] = bb[(c0 + r) * KK + k0 + cl];
        }
        for (int l = tid; l < 64 * KC; l += 64) {
            int r = l >> 5, cl = l & 31;                 // r = n row, cl = k col
            At[cl][r] = ap[(size_t)(n0 + r) * KK + k0 + cl];
        }
        __syncthreads();
#pragma unroll 4
        for (int kk = 0; kk < KC; kk++) {
            float a[8], b[8];
#pragma unroll
            for (int i = 0; i < 8; i++) b[i] = Bt[kk][ty * 8 + i];
#pragma unroll
            for (int j = 0; j < 8; j++) a[j] = At[kk][tx * 8 + j];
#pragma unroll
            for (int i = 0; i < 8; i++)
#pragma unroll
                for (int j = 0; j < 8; j++) acc[i][j] += b[i] * a[j];
        }
        __syncthreads();
    }

    float* op = out + ((size_t)bi * CC + c0) * NN + n0;
#pragma unroll
    for (int i = 0; i < 8; i++) {
        float4 v0 = make_float4(acc[i][0], acc[i][1], acc[i][2], acc[i][3]);
        float4 v1 = make_float4(acc[i][4], acc[i][5], acc[i][6], acc[i][7]);
        *(float4*)(op + (size_t)(ty * 8 + i) * NN + tx * 8) = v0;
        *(float4*)(op + (size_t)(ty * 8 + i) * NN + tx * 8 + 4) = v1;
    }
}

// ---------------------------------------------------------------------------
extern "C" void kernel_launch(void* const* d_in, const int* in_sizes, int n_in,
                              void* d_out, int out_size) {
    const float* feats = (const float*)d_in[0];   // [B, C, H, W] = [16,512,64,64]
    const float* bases = (const float*)d_in[1];   // [1, C, K]    = [1,512,64]
    float* out = (float*)d_out;                   // [B, C, H, W] fp32

    k_bases<<<KK, 128>>>(bases);
    for (int s = 0; s < 3; s++) {
        k_zero<<<(BB * CC * KK + 255) / 256, 256>>>();
        k_gemm1<<<dim3(NN / 64, BB), 64>>>(feats);
        k_gemm2<<<dim3(8, CC / 64, BB), 64>>>(feats);
        k_l2<<<BB * KK, 128>>>();
    }
    k_recon<<<dim3(NN / 64, CC / 64, BB), 64>>>(out);
}

// round 2
// speedup vs baseline: 1.5103x; 1.5103x over previous
#include <cuda_runtime.h>
#include <math.h>

#define BB 16
#define CC 512
#define NN 4096
#define KK 64
#define KC 16
#define NSPLIT 8
#define EPSF 1e-6f

typedef unsigned long long u64;

// Scratch (allocation-free per harness rules)
__device__ float g_b[BB * CC * KK];                    // current bases [bi][c][k]
__device__ float g_bnew[BB * CC * KK];                 // reduced bases pre-l2
__device__ float g_bsplit[NSPLIT * BB * CC * KK];      // per-split GEMM2 partials (16MB)
__device__ float g_colsum[BB * KK];                    // l1-norm denominators
__device__ float g_attn[(size_t)BB * NN * KK];         // attention [bi][n][k] (64MB)

// ---------------- f32x2 helpers (FFMA2 path) ----------------
__device__ __forceinline__ u64 pk2(float lo, float hi) {
    u64 r; asm("mov.b64 %0, {%1,%2};" : "=l"(r) : "f"(lo), "f"(hi)); return r;
}
__device__ __forceinline__ u64 dup2(float v) { return pk2(v, v); }
__device__ __forceinline__ void fma2(u64& d, u64 a, u64 b) {
    asm("fma.rn.f32x2 %0, %1, %2, %3;" : "=l"(d) : "l"(a), "l"(b), "l"(d));
}
__device__ __forceinline__ float2 up2(u64 v) {
    float2 r; asm("mov.b64 {%0,%1}, %2;" : "=f"(r.x), "=f"(r.y) : "l"(v)); return r;
}

// ---------------------------------------------------------------------------
// Normalize input bases (l2 over C) and broadcast to all batches.
__global__ void k_bases(const float* __restrict__ bases) {
    int k = blockIdx.x, t = threadIdx.x;
    __shared__ float red[128];
    float ss = 0.f;
    for (int c = t; c < CC; c += 128) { float v = bases[c * KK + k]; ss += v * v; }
    red[t] = ss; __syncthreads();
    for (int s = 64; s > 0; s >>= 1) { if (t < s) red[t] += red[t + s]; __syncthreads(); }
    float inv = 1.f / (EPSF + sqrtf(red[0]));
    for (int c = t; c < CC; c += 128) {
        float v = bases[c * KK + k] * inv;
        for (int bi = 0; bi < BB; bi++) g_b[(bi * CC + c) * KK + k] = v;
    }
}

__global__ void k_zero_cs() {
    int i = threadIdx.x;
    if (i < BB * KK) g_colsum[i] = 0.f;
}

// ---------------------------------------------------------------------------
// GEMM1: attn[n,k] = softmax_k( sum_c f[c,n]*b[c,k] ), plus column sums over n.
// 128 threads, tile 128n x 64k, micro 8x8 with split k-octet (tx*4 | tx*4+32).
__global__ void __launch_bounds__(128) k_gemm1(const float* __restrict__ f) {
    int bi = blockIdx.y, n0 = blockIdx.x * 128;
    int tid = threadIdx.x, tx = tid & 7, ty = tid >> 3;      // ty: 0..15 (n octet)
    __shared__ float As[KC][132];   // [cc][n]
    __shared__ float Bs[KC][68];    // [cc][k]
    __shared__ float s_cs[KK];
    const float* fb = f + (size_t)bi * CC * NN + n0;
    const float* bb = g_b + bi * CC * KK;

    u64 acc2[8][4];
#pragma unroll
    for (int i = 0; i < 8; i++)
#pragma unroll
        for (int j = 0; j < 4; j++) acc2[i][j] = 0ull;

    for (int c0 = 0; c0 < CC; c0 += KC) {
#pragma unroll
        for (int l = 0; l < 4; l++) {                 // As: 16x128 = 512 float4
            int idx = tid + l * 128;
            int r = idx >> 5, c4 = idx & 31;
            *(float4*)&As[r][c4 * 4] = *(const float4*)&fb[(size_t)(c0 + r) * NN + c4 * 4];
        }
#pragma unroll
        for (int l = 0; l < 2; l++) {                 // Bs: 16x64 = 256 float4
            int idx = tid + l * 128;
            int r = idx >> 4, c4 = idx & 15;
            *(float4*)&Bs[r][c4 * 4] = *(const float4*)&bb[(c0 + r) * KK + c4 * 4];
        }
        __syncthreads();
#pragma unroll
        for (int cc = 0; cc < KC; cc++) {
            float4 a0 = *(float4*)&As[cc][ty * 8];
            float4 a1 = *(float4*)&As[cc][ty * 8 + 4];
            float4 b0 = *(float4*)&Bs[cc][tx * 4];
            float4 b1 = *(float4*)&Bs[cc][tx * 4 + 32];
            u64 bp[4] = { pk2(b0.x, b0.y), pk2(b0.z, b0.w), pk2(b1.x, b1.y), pk2(b1.z, b1.w) };
            float av[8] = { a0.x, a0.y, a0.z, a0.w, a1.x, a1.y, a1.z, a1.w };
#pragma unroll
            for (int i = 0; i < 8; i++) {
                u64 ad = dup2(av[i]);
                fma2(acc2[i][0], ad, bp[0]);
                fma2(acc2[i][1], ad, bp[1]);
                fma2(acc2[i][2], ad, bp[2]);
                fma2(acc2[i][3], ad, bp[3]);
            }
        }
        __syncthreads();
    }

    if (tid < KK) s_cs[tid] = 0.f;
    __syncthreads();

    // Row softmax over k. Thread holds k = {tx*4..+3} U {32+tx*4..+3}; 8 tx lanes = full row.
    float* ap = g_attn + ((size_t)bi * NN + n0) * KK;
    float cssum[8];
#pragma unroll
    for (int j = 0; j < 8; j++) cssum[j] = 0.f;
#pragma unroll
    for (int i = 0; i < 8; i++) {
        float2 e0 = up2(acc2[i][0]), e1 = up2(acc2[i][1]);
        float2 e2 = up2(acc2[i][2]), e3 = up2(acc2[i][3]);
        float v[8] = { e0.x, e0.y, e1.x, e1.y, e2.x, e2.y, e3.x, e3.y };
        float m = v[0];
#pragma unroll
        for (int j = 1; j < 8; j++) m = fmaxf(m, v[j]);
#pragma unroll
        for (int o = 4; o > 0; o >>= 1) m = fmaxf(m, __shfl_xor_sync(0xffffffffu, m, o, 8));
        float s = 0.f;
#pragma unroll
        for (int j = 0; j < 8; j++) { float e = __expf(v[j] - m); v[j] = e; s += e; }
#pragma unroll
        for (int o = 4; o > 0; o >>= 1) s += __shfl_xor_sync(0xffffffffu, s, o, 8);
        float inv = 1.f / s;
#pragma unroll
        for (int j = 0; j < 8; j++) { v[j] *= inv; cssum[j] += v[j]; }
        float* row = ap + (size_t)(ty * 8 + i) * KK;
        *(float4*)(row + tx * 4)      = make_float4(v[0], v[1], v[2], v[3]);
        *(float4*)(row + 32 + tx * 4) = make_float4(v[4], v[5], v[6], v[7]);
    }
#pragma unroll
    for (int j = 0; j < 4; j++) atomicAdd(&s_cs[tx * 4 + j], cssum[j]);
#pragma unroll
    for (int j = 0; j < 4; j++) atomicAdd(&s_cs[32 + tx * 4 + j], cssum[4 + j]);
    __syncthreads();
    if (tid < KK) atomicAdd(&g_colsum[bi * KK + tid], s_cs[tid]);
}

// ---------------------------------------------------------------------------
// GEMM2: bsplit[s][c,k] = sum_{n in split s} f[c,n]*attn[n,k] / (eps+colsum[k])
// 128 threads, tile 128c x 64k, reduction over 512 n per block.
__global__ void __launch_bounds__(128) k_gemm2(const float* __restrict__ f) {
    int bi = blockIdx.z, c0 = blockIdx.y * 128, nbeg = blockIdx.x * (NN / NSPLIT);
    int tid = threadIdx.x, tx = tid & 7, ty = tid >> 3;      // ty: 0..15 (c octet)
    __shared__ float As[KC][132];   // [nn][c]  (transposed f)
    __shared__ float Bs[KC][68];    // [nn][k]
    const float* fr = f + (size_t)bi * CC * NN + (size_t)(c0 + tid) * NN;
    const float* ap = g_attn + (size_t)bi * NN * KK;

    u64 acc2[8][4];
#pragma unroll
    for (int i = 0; i < 8; i++)
#pragma unroll
        for (int j = 0; j < 4; j++) acc2[i][j] = 0ull;

    for (int n0 = nbeg; n0 < nbeg + NN / NSPLIT; n0 += KC) {
        // f transposed: thread tid owns column c = c0+tid, loads 16 n's (64B contig)
        float4 q0 = *(const float4*)&fr[n0];
        float4 q1 = *(const float4*)&fr[n0 + 4];
        float4 q2 = *(const float4*)&fr[n0 + 8];
        float4 q3 = *(const float4*)&fr[n0 + 12];
        As[0][tid] = q0.x;  As[1][tid] = q0.y;  As[2][tid] = q0.z;  As[3][tid] = q0.w;
        As[4][tid] = q1.x;  As[5][tid] = q1.y;  As[6][tid] = q1.z;  As[7][tid] = q1.w;
        As[8][tid] = q2.x;  As[9][tid] = q2.y;  As[10][tid] = q2.z; As[11][tid] = q2.w;
        As[12][tid] = q3.x; As[13][tid] = q3.y; As[14][tid] = q3.z; As[15][tid] = q3.w;
#pragma unroll
        for (int l = 0; l < 2; l++) {                 // attn: 16x64
            int idx = tid + l * 128;
            int r = idx >> 4, c4 = idx & 15;
            *(float4*)&Bs[r][c4 * 4] = *(const float4*)&ap[(size_t)(n0 + r) * KK + c4 * 4];
        }
        __syncthreads();
#pragma unroll
        for (int nn = 0; nn < KC; nn++) {
            float4 a0 = *(float4*)&As[nn][ty * 8];
            float4 a1 = *(float4*)&As[nn][ty * 8 + 4];
            float4 b0 = *(float4*)&Bs[nn][tx * 4];
            float4 b1 = *(float4*)&Bs[nn][tx * 4 + 32];
            u64 bp[4] = { pk2(b0.x, b0.y), pk2(b0.z, b0.w), pk2(b1.x, b1.y), pk2(b1.z, b1.w) };
            float av[8] = { a0.x, a0.y, a0.z, a0.w, a1.x, a1.y, a1.z, a1.w };
#pragma unroll
            for (int i = 0; i < 8; i++) {
                u64 ad = dup2(av[i]);
                fma2(acc2[i][0], ad, bp[0]);
                fma2(acc2[i][1], ad, bp[1]);
                fma2(acc2[i][2], ad, bp[2]);
                fma2(acc2[i][3], ad, bp[3]);
            }
        }
        __syncthreads();
    }

    const float* cs = g_colsum + bi * KK;
    float sc[8];
#pragma unroll
    for (int j = 0; j < 4; j++) sc[j]     = 1.f / (EPSF + cs[tx * 4 + j]);
#pragma unroll
    for (int j = 0; j < 4; j++) sc[4 + j] = 1.f / (EPSF + cs[32 + tx * 4 + j]);

    float* bo = g_bsplit + ((size_t)blockIdx.x * BB + bi) * CC * KK + (size_t)c0 * KK;
#pragma unroll
    for (int i = 0; i < 8; i++) {
        float2 e0 = up2(acc2[i][0]), e1 = up2(acc2[i][1]);
        float2 e2 = up2(acc2[i][2]), e3 = up2(acc2[i][3]);
        float* row = bo + (size_t)(ty * 8 + i) * KK;
        *(float4*)(row + tx * 4)      = make_float4(e0.x * sc[0], e0.y * sc[1], e1.x * sc[2], e1.y * sc[3]);
        *(float4*)(row + 32 + tx * 4) = make_float4(e2.x * sc[4], e2.y * sc[5], e3.x * sc[6], e3.y * sc[7]);
    }
}

// ---------------------------------------------------------------------------
// Sum the NSPLIT partial buffers (fully coalesced).
__global__ void k_reduce() {
    int i = blockIdx.x * blockDim.x + threadIdx.x;
    if (i >= BB * CC * KK) return;
    float s = 0.f;
#pragma unroll
    for (int sp = 0; sp < NSPLIT; sp++) s += g_bsplit[(size_t)sp * BB * CC * KK + i];
    g_bnew[i] = s;
}

// ---------------------------------------------------------------------------
// l2-normalize bnew over C -> g_b
__global__ void k_l2() {
    int bi = blockIdx.x >> 6, k = blockIdx.x & 63, t = threadIdx.x;
    __shared__ float red[128];
    const float* src = g_bnew + bi * CC * KK + k;
    float ss = 0.f;
    for (int c = t; c < CC; c += 128) { float v = src[c * KK]; ss += v * v; }
    red[t] = ss; __syncthreads();
    for (int s = 64; s > 0; s >>= 1) { if (t < s) red[t] += red[t + s]; __syncthreads(); }
    float inv = 1.f / (EPSF + sqrtf(red[0]));
    float* dst = g_b + bi * CC * KK + k;
    for (int c = t; c < CC; c += 128) dst[c * KK] = src[c * KK] * inv;
}

// ---------------------------------------------------------------------------
// Reconstruction: out[c,n] = sum_k b[c,k]*attn[n,k]
// 128 threads, tile 128c x 64n, reduction over K=64 in 4 chunks.
__global__ void __launch_bounds__(128) k_recon(float* __restrict__ out) {
    int bi = blockIdx.z, c0 = blockIdx.y * 128, n0 = blockIdx.x * 64;
    int tid = threadIdx.x, tx = tid & 7, ty = tid >> 3;      // ty: 0..15 (c octet)
    __shared__ float Bt[KC][132];   // [kk][c]
    __shared__ float At[KC][68];    // [kk][n]
    const float* bb = g_b + bi * CC * KK;
    const float* ap = g_attn + (size_t)bi * NN * KK;

    u64 acc2[8][4];
#pragma unroll
    for (int i = 0; i < 8; i++)
#pragma unroll
        for (int j = 0; j < 4; j++) acc2[i][j] = 0ull;

    for (int k0 = 0; k0 < KK; k0 += KC) {
        {   // Bt: b[c][k] -> Bt[k][c]; thread owns c = c0+tid, 16 k's (64B contig)
            const float* br = bb + (size_t)(c0 + tid) * KK + k0;
            float4 q0 = *(const float4*)&br[0];
            float4 q1 = *(const float4*)&br[4];
            float4 q2 = *(const float4*)&br[8];
            float4 q3 = *(const float4*)&br[12];
            Bt[0][tid] = q0.x;  Bt[1][tid] = q0.y;  Bt[2][tid] = q0.z;  Bt[3][tid] = q0.w;
            Bt[4][tid] = q1.x;  Bt[5][tid] = q1.y;  Bt[6][tid] = q1.z;  Bt[7][tid] = q1.w;
            Bt[8][tid] = q2.x;  Bt[9][tid] = q2.y;  Bt[10][tid] = q2.z; Bt[11][tid] = q2.w;
            Bt[12][tid] = q3.x; Bt[13][tid] = q3.y; Bt[14][tid] = q3.z; Bt[15][tid] = q3.w;
        }
        {   // At: attn[n][k] -> At[k][n]; pair of threads per n, 8 k's each (32B)
            int n = tid >> 1, kq = (tid & 1) * 8;
            const float* ar = ap + (size_t)(n0 + n) * KK + k0 + kq;
            float4 q0 = *(const float4*)&ar[0];
            float4 q1 = *(const float4*)&ar[4];
            At[kq + 0][n] = q0.x; At[kq + 1][n] = q0.y; At[kq + 2][n] = q0.z; At[kq + 3][n] = q0.w;
            At[kq + 4][n] = q1.x; At[kq + 5][n] = q1.y; At[kq + 6][n] = q1.z; At[kq + 7][n] = q1.w;
        }
        __syncthreads();
#pragma unroll
        for (int kk = 0; kk < KC; kk++) {
            float4 a0 = *(float4*)&Bt[kk][ty * 8];
            float4 a1 = *(float4*)&Bt[kk][ty * 8 + 4];
            float4 b0 = *(float4*)&At[kk][tx * 4];
            float4 b1 = *(float4*)&At[kk][tx * 4 + 32];
            u64 bp[4] = { pk2(b0.x, b0.y), pk2(b0.z, b0.w), pk2(b1.x, b1.y), pk2(b1.z, b1.w) };
            float av[8] = { a0.x, a0.y, a0.z, a0.w, a1.x, a1.y, a1.z, a1.w };
#pragma unroll
            for (int i = 0; i < 8; i++) {
                u64 ad = dup2(av[i]);
                fma2(acc2[i][0], ad, bp[0]);
                fma2(acc2[i][1], ad, bp[1]);
                fma2(acc2[i][2], ad, bp[2]);
                fma2(acc2[i][3], ad, bp[3]);
            }
        }
        __syncthreads();
    }

    float* op = out + ((size_t)bi * CC + c0) * NN + n0;
#pragma unroll
    for (int i = 0; i < 8; i++) {
        float2 e0 = up2(acc2[i][0]), e1 = up2(acc2[i][1]);
        float2 e2 = up2(acc2[i][2]), e3 = up2(acc2[i][3]);
        float* row = op + (size_t)(ty * 8 + i) * NN;
        *(float4*)(row + tx * 4)      = make_float4(e0.x, e0.y, e1.x, e1.y);
        *(float4*)(row + 32 + tx * 4) = make_float4(e2.x, e2.y, e3.x, e3.y);
    }
}

// ---------------------------------------------------------------------------
extern "C" void kernel_launch(void* const* d_in, const int* in_sizes, int n_in,
                              void* d_out, int out_size) {
    const float* feats = (const float*)d_in[0];   // [16,512,64,64]
    const float* bases = (const float*)d_in[1];   // [1,512,64]
    float* out = (float*)d_out;

    k_bases<<<KK, 128>>>(bases);
    for (int s = 0; s < 3; s++) {
        k_zero_cs<<<1, 1024>>>();
        k_gemm1<<<dim3(NN / 128, BB), 128>>>(feats);
        k_gemm2<<<dim3(NSPLIT, CC / 128, BB), 128>>>(feats);
        k_reduce<<<(BB * CC * KK + 255) / 256, 256>>>();
        k_l2<<<BB * KK, 128>>>();
    }
    k_recon<<<dim3(NN / 64, CC / 128, BB), 128>>>(out);
}